// round 3
// baseline (speedup 1.0000x reference)
#include <cuda_runtime.h>
#include <cuda_bf16.h>
#include <cstdint>
#include <cstddef>

#define NN     4096
#define IND    128
#define OUTD   64
#define KSPLIT 4
#define MTILE  128
#define KTILE  64

// ---------------- scratch (device globals; no allocation allowed) ----------
__device__ __align__(16) __nv_bfloat16 g_Wh[2][NN][OUTD];   // Wh, bf16 row-major
__device__ float g_si[2][NN];
__device__ float g_sj[2][NN];
__device__ float g_num[2][KSPLIT][NN * OUTD];               // partial numerators
__device__ float g_Z[2][KSPLIT][NN];                        // partial row sums

__device__ __forceinline__ uint32_t smem_u32(const void* p) {
    return (uint32_t)__cvta_generic_to_shared(p);
}

// ---------------- prep: Wh = H@W (fp32) -> bf16; s_i, s_j -------------------
__global__ void __launch_bounds__(256) gat_prep(
    const float* __restrict__ H, const float* __restrict__ W0,
    const float* __restrict__ W1, const float* __restrict__ a0,
    const float* __restrict__ a1)
{
    const int rel = blockIdx.y;
    const int i0  = blockIdx.x * 64;
    const float* W  = rel ? W1 : W0;
    const float* av = rel ? a1 : a0;

    __shared__ float Hs[64][132];  // padded
    const int tid = threadIdx.x;
    for (int idx = tid; idx < 64 * IND; idx += 256) {
        int r = idx >> 7, k = idx & 127;
        Hs[r][k] = H[(size_t)(i0 + r) * IND + k];
    }
    __syncthreads();

    const int tx = tid & 15, ty = tid >> 4;   // 16x16 threads, 4x4 micro-tile
    float acc[4][4] = {};
#pragma unroll 4
    for (int k = 0; k < IND; ++k) {
        float4 b = __ldg((const float4*)(W + (size_t)k * OUTD + tx * 4));
#pragma unroll
        for (int r = 0; r < 4; ++r) {
            float h = Hs[ty * 4 + r][k];
            acc[r][0] += h * b.x; acc[r][1] += h * b.y;
            acc[r][2] += h * b.z; acc[r][3] += h * b.w;
        }
    }
    float alo[4], ahi[4];
#pragma unroll
    for (int c = 0; c < 4; ++c) {
        alo[c] = __ldg(av + tx * 4 + c);
        ahi[c] = __ldg(av + OUTD + tx * 4 + c);
    }
#pragma unroll
    for (int r = 0; r < 4; ++r) {
        int gi = i0 + ty * 4 + r;
#pragma unroll
        for (int c = 0; c < 4; ++c)
            g_Wh[rel][gi][tx * 4 + c] = __float2bfloat16(acc[r][c]);
        float psi = acc[r][0]*alo[0] + acc[r][1]*alo[1] + acc[r][2]*alo[2] + acc[r][3]*alo[3];
        float psj = acc[r][0]*ahi[0] + acc[r][1]*ahi[1] + acc[r][2]*ahi[2] + acc[r][3]*ahi[3];
#pragma unroll
        for (int o = 8; o; o >>= 1) {
            psi += __shfl_down_sync(0xffffffffu, psi, o, 16);
            psj += __shfl_down_sync(0xffffffffu, psj, o, 16);
        }
        if (tx == 0) { g_si[rel][gi] = psi; g_sj[rel][gi] = psj; }
    }
}

// ---------------- main: fused masked-exp + P@Wh via mma.sync ---------------
__device__ __forceinline__ float lrexp(float t, int m) {
    t = t > 0.f ? t : 0.2f * t;
    return __expf(t) * (float)m;     // m in {0,1}
}
__device__ __forceinline__ uint32_t packbf2(float lo, float hi) {
    __nv_bfloat162 v = __floats2bfloat162_rn(lo, hi);
    return *(uint32_t*)&v;
}
__device__ __forceinline__ void mma16816(float* c, uint32_t a0, uint32_t a1,
                                         uint32_t a2, uint32_t a3,
                                         uint32_t b0, uint32_t b1) {
    asm volatile("mma.sync.aligned.m16n8k16.row.col.f32.bf16.bf16.f32 "
                 "{%0,%1,%2,%3}, {%4,%5,%6,%7}, {%8,%9}, {%0,%1,%2,%3};"
                 : "+f"(c[0]), "+f"(c[1]), "+f"(c[2]), "+f"(c[3])
                 : "r"(a0), "r"(a1), "r"(a2), "r"(a3), "r"(b0), "r"(b1));
}

__global__ void __launch_bounds__(256) gat_main(const int* __restrict__ A0,
                                                const int* __restrict__ A1)
{
    __shared__ __nv_bfloat16 Bs[KTILE][72];      // +8 pad: conflict-free ldmatrix
    __shared__ float sjs[NN / KSPLIT];           // 4 KB

    const int i0  = blockIdx.x * MTILE;
    const int ksp = blockIdx.y;
    const int rel = blockIdx.z;
    const int* __restrict__ A = rel ? A1 : A0;

    const int tid = threadIdx.x;
    const int w = tid >> 5, lane = tid & 31;
    const int kbase = ksp * (NN / KSPLIT);

    for (int i = tid; i < NN / KSPLIT; i += 256) sjs[i] = g_sj[rel][kbase + i];

    const int r  = lane >> 2;            // 0..7
    const int c0 = (lane & 3) * 2;       // 0,2,4,6
    const int row0 = i0 + w * 16 + r;
    const int row1 = row0 + 8;
    const float si0 = g_si[rel][row0];
    const float si1 = g_si[rel][row1];

    float acc[8][4];
#pragma unroll
    for (int nt = 0; nt < 8; ++nt)
#pragma unroll
        for (int q = 0; q < 4; ++q) acc[nt][q] = 0.f;
    float z0 = 0.f, z1 = 0.f;

    const __nv_bfloat16* __restrict__ whb = &g_Wh[rel][0][0];
    const int ntiles = (NN / KSPLIT) / KTILE;    // 16

    for (int t = 0; t < ntiles; ++t) {
        const int k0 = kbase + t * KTILE;
        __syncthreads();
        // stage Wh[k0..k0+63][0..63] -> Bs
        for (int idx = tid; idx < KTILE * 8; idx += 256) {
            int kr = idx >> 3, ch = idx & 7;
            *(int4*)&Bs[kr][ch * 8] =
                *(const int4*)(whb + (size_t)(k0 + kr) * OUTD + ch * 8);
        }
        __syncthreads();

#pragma unroll
        for (int f = 0; f < 4; ++f) {
            const int kc = t * KTILE + f * 16 + c0;  // index into sjs
            const int gc = k0 + f * 16 + c0;         // global col
            // adjacency for this lane's fragment slots
            int2 m00 = *(const int2*)(A + (size_t)row0 * NN + gc);
            int2 m10 = *(const int2*)(A + (size_t)row1 * NN + gc);
            int2 m01 = *(const int2*)(A + (size_t)row0 * NN + gc + 8);
            int2 m11 = *(const int2*)(A + (size_t)row1 * NN + gc + 8);
            float sja = sjs[kc], sjb = sjs[kc + 1];
            float sjc = sjs[kc + 8], sjd = sjs[kc + 9];

            float p00a = lrexp(si0 + sja, m00.x), p00b = lrexp(si0 + sjb, m00.y);
            float p10a = lrexp(si1 + sja, m10.x), p10b = lrexp(si1 + sjb, m10.y);
            float p01a = lrexp(si0 + sjc, m01.x), p01b = lrexp(si0 + sjd, m01.y);
            float p11a = lrexp(si1 + sjc, m11.x), p11b = lrexp(si1 + sjd, m11.y);
            z0 += p00a + p00b + p01a + p01b;
            z1 += p10a + p10b + p11a + p11b;

            // A fragment (m16k16, row-major): a0=(r,c0..c0+1) a1=(r+8,..)
            // a2=(r,c0+8..) a3=(r+8,c0+8..)
            uint32_t a0 = packbf2(p00a, p00b);
            uint32_t a1 = packbf2(p10a, p10b);
            uint32_t a2 = packbf2(p01a, p01b);
            uint32_t a3 = packbf2(p11a, p11b);

#pragma unroll
            for (int nt = 0; nt < 4; ++nt) {
                uint32_t b0, b1, b2, b3;
                uint32_t addr = smem_u32(
                    &Bs[f * 16 + (lane & 15)][nt * 16 + (lane >> 4) * 8]);
                asm volatile(
                    "ldmatrix.sync.aligned.m8n8.x4.trans.shared.b16 "
                    "{%0,%1,%2,%3}, [%4];"
                    : "=r"(b0), "=r"(b1), "=r"(b2), "=r"(b3) : "r"(addr));
                mma16816(acc[2 * nt],     a0, a1, a2, a3, b0, b1);
                mma16816(acc[2 * nt + 1], a0, a1, a2, a3, b2, b3);
            }
        }
    }

    // Z: reduce within quad (lanes 4r..4r+3 hold row r / r+8 partials)
    z0 += __shfl_xor_sync(0xffffffffu, z0, 1);
    z0 += __shfl_xor_sync(0xffffffffu, z0, 2);
    z1 += __shfl_xor_sync(0xffffffffu, z1, 1);
    z1 += __shfl_xor_sync(0xffffffffu, z1, 2);
    if ((lane & 3) == 0) {
        g_Z[rel][ksp][row0] = z0;
        g_Z[rel][ksp][row1] = z1;
    }

    // store accumulators: acc[nt] -> (row0,row1) x cols nt*8 + c0 (+1)
    float* __restrict__ num = &g_num[rel][ksp][0];
#pragma unroll
    for (int nt = 0; nt < 8; ++nt) {
        int col = nt * 8 + c0;
        *(float2*)&num[(size_t)row0 * OUTD + col] = make_float2(acc[nt][0], acc[nt][1]);
        *(float2*)&num[(size_t)row1 * OUTD + col] = make_float2(acc[nt][2], acc[nt][3]);
    }
}

// ---------------- combine: out = sum_rel num/Z + bias -----------------------
__global__ void __launch_bounds__(256) gat_combine(const float* __restrict__ bias,
                                                   float* __restrict__ out)
{
    const int idx = blockIdx.x * 256 + threadIdx.x;   // 262144 total
    const int i = idx >> 6, c = idx & 63;
    float r = bias[c];
#pragma unroll
    for (int rel = 0; rel < 2; ++rel) {
        float ns = 0.f, zs = 0.f;
#pragma unroll
        for (int ks = 0; ks < KSPLIT; ++ks) {
            ns += g_num[rel][ks][idx];
            zs += g_Z[rel][ks][i];
        }
        r += (zs > 0.f) ? ns / zs : 0.f;
    }
    out[idx] = r;
}

// ---------------- launch ----------------------------------------------------
extern "C" void kernel_launch(void* const* d_in, const int* in_sizes, int n_in,
                              void* d_out, int out_size) {
    const float* H    = (const float*)d_in[0];
    const int*   A0   = (const int*)  d_in[1];
    const int*   A1   = (const int*)  d_in[2];
    const float* W0   = (const float*)d_in[3];
    const float* W1   = (const float*)d_in[4];
    const float* a0   = (const float*)d_in[5];
    const float* a1   = (const float*)d_in[6];
    const float* bias = (const float*)d_in[7];
    float* out = (float*)d_out;

    gat_prep<<<dim3(NN / 64, 2), 256>>>(H, W0, W1, a0, a1);
    gat_main<<<dim3(NN / MTILE, KSPLIT, 2), 256>>>(A0, A1);
    gat_combine<<<(NN * OUTD) / 256, 256>>>(bias, out);
}

// round 4
// speedup vs baseline: 1.4416x; 1.4416x over previous
#include <cuda_runtime.h>
#include <cuda_bf16.h>
#include <cstdint>
#include <cstddef>

#define NN     4096
#define IND    128
#define OUTD   64
#define KSPLIT 4
#define MTILE  128
#define KTILE  64

// ---------------- scratch (device globals; no allocation allowed) ----------
__device__ __align__(16) __nv_bfloat16 g_Wh[2][NN][OUTD];   // Wh, bf16 row-major
__device__ float g_si[2][NN];                               // pre-scaled by log2(e)
__device__ float g_sj[2][NN];                               // pre-scaled by log2(e)
__device__ float g_num[2][KSPLIT][NN * OUTD];               // partial numerators
__device__ float g_Z[2][KSPLIT][NN];                        // partial row sums

__device__ __forceinline__ uint32_t smem_u32(const void* p) {
    return (uint32_t)__cvta_generic_to_shared(p);
}

// ---------------- prep: Wh = H@W (fp32) -> bf16; s_i, s_j -------------------
__global__ void __launch_bounds__(256) gat_prep(
    const float* __restrict__ H, const float* __restrict__ W0,
    const float* __restrict__ W1, const float* __restrict__ a0,
    const float* __restrict__ a1)
{
    const int rel = blockIdx.y;
    const int i0  = blockIdx.x * 64;
    const float* __restrict__ W  = rel ? W1 : W0;
    const float* __restrict__ av = rel ? a1 : a0;

    __shared__ float Hs[64][68];   // 64 rows x 64 k (per k-tile), padded
    __shared__ float Ws[64][68];   // 64 k x 64 cols (per k-tile), padded
    __shared__ float as_[2 * OUTD];

    const int tid = threadIdx.x;
    if (tid < 2 * OUTD) as_[tid] = av[tid];

    const int tx = tid & 15, ty = tid >> 4;   // 16x16 threads, 4x4 micro-tile
    float acc[4][4] = {};

#pragma unroll
    for (int kt = 0; kt < 2; ++kt) {
        __syncthreads();
        // stage H[i0..i0+63][kt*64 .. kt*64+63]
        for (int idx = tid; idx < 64 * 16; idx += 256) {
            int r = idx >> 4, c4 = idx & 15;
            float4 v = *(const float4*)(H + (size_t)(i0 + r) * IND + kt * 64 + c4 * 4);
            Hs[r][c4 * 4 + 0] = v.x; Hs[r][c4 * 4 + 1] = v.y;
            Hs[r][c4 * 4 + 2] = v.z; Hs[r][c4 * 4 + 3] = v.w;
        }
        // stage W[kt*64 .. kt*64+63][0..63]
        for (int idx = tid; idx < 64 * 16; idx += 256) {
            int k = idx >> 4, c4 = idx & 15;
            float4 v = *(const float4*)(W + (size_t)(kt * 64 + k) * OUTD + c4 * 4);
            Ws[k][c4 * 4 + 0] = v.x; Ws[k][c4 * 4 + 1] = v.y;
            Ws[k][c4 * 4 + 2] = v.z; Ws[k][c4 * 4 + 3] = v.w;
        }
        __syncthreads();
#pragma unroll 8
        for (int k = 0; k < 64; ++k) {
            float4 b = *(const float4*)&Ws[k][tx * 4];
#pragma unroll
            for (int r = 0; r < 4; ++r) {
                float h = Hs[ty * 4 + r][k];
                acc[r][0] += h * b.x; acc[r][1] += h * b.y;
                acc[r][2] += h * b.z; acc[r][3] += h * b.w;
            }
        }
    }

    float alo[4], ahi[4];
#pragma unroll
    for (int c = 0; c < 4; ++c) {
        alo[c] = as_[tx * 4 + c];
        ahi[c] = as_[OUTD + tx * 4 + c];
    }
    const float LOG2E = 1.4426950408889634f;
#pragma unroll
    for (int r = 0; r < 4; ++r) {
        int gi = i0 + ty * 4 + r;
#pragma unroll
        for (int c = 0; c < 4; ++c)
            g_Wh[rel][gi][tx * 4 + c] = __float2bfloat16(acc[r][c]);
        float psi = acc[r][0]*alo[0] + acc[r][1]*alo[1] + acc[r][2]*alo[2] + acc[r][3]*alo[3];
        float psj = acc[r][0]*ahi[0] + acc[r][1]*ahi[1] + acc[r][2]*ahi[2] + acc[r][3]*ahi[3];
#pragma unroll
        for (int o = 8; o; o >>= 1) {
            psi += __shfl_down_sync(0xffffffffu, psi, o, 16);
            psj += __shfl_down_sync(0xffffffffu, psj, o, 16);
        }
        if (tx == 0) { g_si[rel][gi] = psi * LOG2E; g_sj[rel][gi] = psj * LOG2E; }
    }
}

// ---------------- main: fused masked-exp + P@Wh via mma.sync ---------------
// Inputs si/sj are pre-scaled by log2(e); lrelu commutes with positive scale,
// so exp(lrelu(si+sj)) == ex2(lrelu(si'+sj')).
__device__ __forceinline__ float lrexp2(float t, int m) {
    t = fmaxf(t, 0.2f * t);
    float e;
    asm("ex2.approx.f32 %0, %1;" : "=f"(e) : "f"(t));
    return e * __int_as_float(m * 0x3f800000);   // m in {0,1}
}
__device__ __forceinline__ uint32_t packbf2(float lo, float hi) {
    __nv_bfloat162 v = __floats2bfloat162_rn(lo, hi);
    return *(uint32_t*)&v;
}
__device__ __forceinline__ void mma16816(float* c, uint32_t a0, uint32_t a1,
                                         uint32_t a2, uint32_t a3,
                                         uint32_t b0, uint32_t b1) {
    asm volatile("mma.sync.aligned.m16n8k16.row.col.f32.bf16.bf16.f32 "
                 "{%0,%1,%2,%3}, {%4,%5,%6,%7}, {%8,%9}, {%0,%1,%2,%3};"
                 : "+f"(c[0]), "+f"(c[1]), "+f"(c[2]), "+f"(c[3])
                 : "r"(a0), "r"(a1), "r"(a2), "r"(a3), "r"(b0), "r"(b1));
}

__global__ void __launch_bounds__(256, 2) gat_main(const int* __restrict__ A0,
                                                   const int* __restrict__ A1)
{
    __shared__ __nv_bfloat16 Bs[KTILE][72];      // +8 pad: conflict-free ldmatrix
    __shared__ float sjs[NN / KSPLIT];           // 4 KB

    const int i0  = blockIdx.x * MTILE;
    const int ksp = blockIdx.y;
    const int rel = blockIdx.z;
    const int* __restrict__ A = rel ? A1 : A0;

    const int tid = threadIdx.x;
    const int w = tid >> 5, lane = tid & 31;
    const int kbase = ksp * (NN / KSPLIT);

    for (int i = tid; i < NN / KSPLIT; i += 256) sjs[i] = g_sj[rel][kbase + i];

    const int r  = lane >> 2;            // 0..7
    const int c0 = (lane & 3) * 2;       // 0,2,4,6
    const int row0 = i0 + w * 16 + r;
    const int row1 = row0 + 8;
    const float si0 = g_si[rel][row0];
    const float si1 = g_si[rel][row1];
    const int* __restrict__ Ar0 = A + (size_t)row0 * NN;
    const int* __restrict__ Ar1 = A + (size_t)row1 * NN;

    float acc[8][4];
#pragma unroll
    for (int nt = 0; nt < 8; ++nt)
#pragma unroll
        for (int q = 0; q < 4; ++q) acc[nt][q] = 0.f;
    float z0 = 0.f, z1 = 0.f;

    const __nv_bfloat16* __restrict__ whb = &g_Wh[rel][0][0];
    const int ntiles = (NN / KSPLIT) / KTILE;    // 16

    for (int t = 0; t < ntiles; ++t) {
        const int k0 = kbase + t * KTILE;
        __syncthreads();
        // stage Wh[k0..k0+63][0..63] -> Bs
        for (int idx = tid; idx < KTILE * 8; idx += 256) {
            int kr = idx >> 3, ch = idx & 7;
            *(int4*)&Bs[kr][ch * 8] =
                *(const int4*)(whb + (size_t)(k0 + kr) * OUTD + ch * 8);
        }
        __syncthreads();

#pragma unroll
        for (int f = 0; f < 4; ++f) {
            const int kc = t * KTILE + f * 16 + c0;  // index into sjs
            const int gc = k0 + f * 16 + c0;         // global col
            // adjacency for this lane's fragment slots
            int2 m00 = *(const int2*)(Ar0 + gc);
            int2 m10 = *(const int2*)(Ar1 + gc);
            int2 m01 = *(const int2*)(Ar0 + gc + 8);
            int2 m11 = *(const int2*)(Ar1 + gc + 8);
            float2 sjab = *(const float2*)&sjs[kc];
            float2 sjcd = *(const float2*)&sjs[kc + 8];

            float p00a = lrexp2(si0 + sjab.x, m00.x), p00b = lrexp2(si0 + sjab.y, m00.y);
            float p10a = lrexp2(si1 + sjab.x, m10.x), p10b = lrexp2(si1 + sjab.y, m10.y);
            float p01a = lrexp2(si0 + sjcd.x, m01.x), p01b = lrexp2(si0 + sjcd.y, m01.y);
            float p11a = lrexp2(si1 + sjcd.x, m11.x), p11b = lrexp2(si1 + sjcd.y, m11.y);
            z0 += p00a + p00b + p01a + p01b;
            z1 += p10a + p10b + p11a + p11b;

            // A fragment (m16k16, row-major)
            uint32_t a0 = packbf2(p00a, p00b);
            uint32_t a1 = packbf2(p10a, p10b);
            uint32_t a2 = packbf2(p01a, p01b);
            uint32_t a3 = packbf2(p11a, p11b);

#pragma unroll
            for (int nt = 0; nt < 4; ++nt) {
                uint32_t b0, b1, b2, b3;
                uint32_t addr = smem_u32(
                    &Bs[f * 16 + (lane & 15)][nt * 16 + (lane >> 4) * 8]);
                asm volatile(
                    "ldmatrix.sync.aligned.m8n8.x4.trans.shared.b16 "
                    "{%0,%1,%2,%3}, [%4];"
                    : "=r"(b0), "=r"(b1), "=r"(b2), "=r"(b3) : "r"(addr));
                mma16816(acc[2 * nt],     a0, a1, a2, a3, b0, b1);
                mma16816(acc[2 * nt + 1], a0, a1, a2, a3, b2, b3);
            }
        }
    }

    // Z: reduce within quad (lanes 4r..4r+3 hold row r / r+8 partials)
    z0 += __shfl_xor_sync(0xffffffffu, z0, 1);
    z0 += __shfl_xor_sync(0xffffffffu, z0, 2);
    z1 += __shfl_xor_sync(0xffffffffu, z1, 1);
    z1 += __shfl_xor_sync(0xffffffffu, z1, 2);
    if ((lane & 3) == 0) {
        g_Z[rel][ksp][row0] = z0;
        g_Z[rel][ksp][row1] = z1;
    }

    // store accumulators: acc[nt] -> (row0,row1) x cols nt*8 + c0 (+1)
    float* __restrict__ num = &g_num[rel][ksp][0];
#pragma unroll
    for (int nt = 0; nt < 8; ++nt) {
        int col = nt * 8 + c0;
        *(float2*)&num[(size_t)row0 * OUTD + col] = make_float2(acc[nt][0], acc[nt][1]);
        *(float2*)&num[(size_t)row1 * OUTD + col] = make_float2(acc[nt][2], acc[nt][3]);
    }
}

// ---------------- combine: out = sum_rel num/Z + bias -----------------------
__global__ void __launch_bounds__(256) gat_combine(const float* __restrict__ bias,
                                                   float* __restrict__ out)
{
    const int idx = blockIdx.x * 256 + threadIdx.x;   // 262144 total
    const int i = idx >> 6, c = idx & 63;
    float r = bias[c];
#pragma unroll
    for (int rel = 0; rel < 2; ++rel) {
        float ns = 0.f, zs = 0.f;
#pragma unroll
        for (int ks = 0; ks < KSPLIT; ++ks) {
            ns += g_num[rel][ks][idx];
            zs += g_Z[rel][ks][i];
        }
        r += (zs > 0.f) ? ns / zs : 0.f;
    }
    out[idx] = r;
}

// ---------------- launch ----------------------------------------------------
extern "C" void kernel_launch(void* const* d_in, const int* in_sizes, int n_in,
                              void* d_out, int out_size) {
    const float* H    = (const float*)d_in[0];
    const int*   A0   = (const int*)  d_in[1];
    const int*   A1   = (const int*)  d_in[2];
    const float* W0   = (const float*)d_in[3];
    const float* W1   = (const float*)d_in[4];
    const float* a0   = (const float*)d_in[5];
    const float* a1   = (const float*)d_in[6];
    const float* bias = (const float*)d_in[7];
    float* out = (float*)d_out;

    gat_prep<<<dim3(NN / 64, 2), 256>>>(H, W0, W1, a0, a1);
    gat_main<<<dim3(NN / MTILE, KSPLIT, 2), 256>>>(A0, A1);
    gat_combine<<<(NN * OUTD) / 256, 256>>>(bias, out);
}